// round 1
// baseline (speedup 1.0000x reference)
#include <cuda_runtime.h>

#define BB 4
#define SS 2048
#define EE 1024
#define HH 16
#define DD 64
#define MROWS (BB * SS)   // 8192

// Scratch (device globals: allocation-free rule)
__device__ float g_q[BB * HH * SS * DD];    // 33.5 MB, q pre-scaled by 1/8
__device__ float g_k[BB * HH * SS * DD];
__device__ float g_v[BB * HH * SS * DD];
__device__ float g_att[BB * SS * EE];       // attention output, [B,S,E]

// ---------------------------------------------------------------------------
// GEMM: C[M,N] = A[M,K] @ W[N,K]^T + bias
// MODE 0: A = x (param), epilogue scatters into g_q/g_k/g_v (N must be 3072)
// MODE 1: A = g_att (internal), epilogue writes Cp (d_out) with bias
// Tiles: 128x128x16, 256 threads, 8x8 per-thread microtile, smem double buffer
// ---------------------------------------------------------------------------
template <int MODE>
__global__ __launch_bounds__(256) void gemm_kernel(
    const float* __restrict__ Ap, const float* __restrict__ Wp,
    const float* __restrict__ bias, float* __restrict__ Cp,
    int M, int N, int K)
{
    __shared__ float As[2][16][128];
    __shared__ float Bs[2][16][128];

    const float* A = (MODE == 1) ? (const float*)g_att : Ap;

    const int tid = threadIdx.x;
    const int tx = tid & 15;          // 0..15
    const int ty = tid >> 4;          // 0..15
    const int bm = blockIdx.y;
    const int bn = blockIdx.x;

    const int lm = tid >> 2;          // 0..63
    const int lk = (tid & 3) << 2;    // 0,4,8,12

    const float* Ag0 = A  + (bm * 128 + lm) * K + lk;
    const float* Ag1 = Ag0 + 64 * K;
    const float* Wg0 = Wp + (bn * 128 + lm) * K + lk;
    const float* Wg1 = Wg0 + 64 * K;

    float acc[8][8];
#pragma unroll
    for (int i = 0; i < 8; ++i)
#pragma unroll
        for (int j = 0; j < 8; ++j) acc[i][j] = 0.f;

#define STORE_TILE(buf, va0, va1, vb0, vb1)                                   \
    do {                                                                      \
        As[buf][lk + 0][lm] = (va0).x;  As[buf][lk + 1][lm] = (va0).y;        \
        As[buf][lk + 2][lm] = (va0).z;  As[buf][lk + 3][lm] = (va0).w;        \
        As[buf][lk + 0][lm + 64] = (va1).x; As[buf][lk + 1][lm + 64] = (va1).y;\
        As[buf][lk + 2][lm + 64] = (va1).z; As[buf][lk + 3][lm + 64] = (va1).w;\
        Bs[buf][lk + 0][lm] = (vb0).x;  Bs[buf][lk + 1][lm] = (vb0).y;        \
        Bs[buf][lk + 2][lm] = (vb0).z;  Bs[buf][lk + 3][lm] = (vb0).w;        \
        Bs[buf][lk + 0][lm + 64] = (vb1).x; Bs[buf][lk + 1][lm + 64] = (vb1).y;\
        Bs[buf][lk + 2][lm + 64] = (vb1).z; Bs[buf][lk + 3][lm + 64] = (vb1).w;\
    } while (0)

    // preload k-tile 0
    {
        float4 a0 = *(const float4*)Ag0;
        float4 a1 = *(const float4*)Ag1;
        float4 b0 = *(const float4*)Wg0;
        float4 b1 = *(const float4*)Wg1;
        STORE_TILE(0, a0, a1, b0, b1);
    }
    __syncthreads();

    const int nt = K >> 4;
    for (int kt = 0; kt < nt; ++kt) {
        const int cur = kt & 1;
        float4 na0, na1, nb0, nb1;
        const bool have_next = (kt + 1 < nt);
        if (have_next) {
            const int off = (kt + 1) << 4;
            na0 = *(const float4*)(Ag0 + off);
            na1 = *(const float4*)(Ag1 + off);
            nb0 = *(const float4*)(Wg0 + off);
            nb1 = *(const float4*)(Wg1 + off);
        }
#pragma unroll
        for (int kk = 0; kk < 16; ++kk) {
            float4 af0 = *(const float4*)&As[cur][kk][ty << 2];
            float4 af1 = *(const float4*)&As[cur][kk][64 + (ty << 2)];
            float4 bf0 = *(const float4*)&Bs[cur][kk][tx << 2];
            float4 bf1 = *(const float4*)&Bs[cur][kk][64 + (tx << 2)];
            float ar[8] = {af0.x, af0.y, af0.z, af0.w, af1.x, af1.y, af1.z, af1.w};
            float br[8] = {bf0.x, bf0.y, bf0.z, bf0.w, bf1.x, bf1.y, bf1.z, bf1.w};
#pragma unroll
            for (int i = 0; i < 8; ++i)
#pragma unroll
                for (int j = 0; j < 8; ++j)
                    acc[i][j] = fmaf(ar[i], br[j], acc[i][j]);
        }
        if (have_next) {
            STORE_TILE(cur ^ 1, na0, na1, nb0, nb1);
        }
        __syncthreads();
    }
#undef STORE_TILE

    // ---------------- epilogue ----------------
    if (MODE == 1) {
#pragma unroll
        for (int ii = 0; ii < 2; ++ii) {
#pragma unroll
            for (int i = 0; i < 4; ++i) {
                const int gm = bm * 128 + ii * 64 + (ty << 2) + i;
#pragma unroll
                for (int jj = 0; jj < 2; ++jj) {
                    const int cn = bn * 128 + jj * 64 + (tx << 2);
                    const float4 bv = *(const float4*)(bias + cn);
                    float4 r;
                    r.x = acc[ii * 4 + i][jj * 4 + 0] + bv.x;
                    r.y = acc[ii * 4 + i][jj * 4 + 1] + bv.y;
                    r.z = acc[ii * 4 + i][jj * 4 + 2] + bv.z;
                    r.w = acc[ii * 4 + i][jj * 4 + 3] + bv.w;
                    *(float4*)(Cp + gm * N + cn) = r;
                }
            }
        }
    } else {
        // scatter into g_q/g_k/g_v; layout [B,H,S,DD]
#pragma unroll
        for (int ii = 0; ii < 2; ++ii) {
#pragma unroll
            for (int i = 0; i < 4; ++i) {
                const int gm = bm * 128 + ii * 64 + (ty << 2) + i;
                const int b = gm >> 11;        // / 2048
                const int s = gm & 2047;
#pragma unroll
                for (int jj = 0; jj < 2; ++jj) {
                    const int cg = bn * 2 + jj;      // 64-col group, 0..47
                    const int h = cg / 3;
                    const int c = cg % 3;            // 0=q 1=k 2=v
                    const int d = tx << 2;
                    const float4 bv = *(const float4*)(bias + cg * 64 + d);
                    float4 r;
                    r.x = acc[ii * 4 + i][jj * 4 + 0] + bv.x;
                    r.y = acc[ii * 4 + i][jj * 4 + 1] + bv.y;
                    r.z = acc[ii * 4 + i][jj * 4 + 2] + bv.z;
                    r.w = acc[ii * 4 + i][jj * 4 + 3] + bv.w;
                    float* dst;
                    if (c == 0) {
                        r.x *= 0.125f; r.y *= 0.125f; r.z *= 0.125f; r.w *= 0.125f;
                        dst = g_q;
                    } else if (c == 1) {
                        dst = g_k;
                    } else {
                        dst = g_v;
                    }
                    *(float4*)(dst + ((b * HH + h) * SS + s) * DD + d) = r;
                }
            }
        }
    }
}

// ---------------------------------------------------------------------------
// Flash attention (causal). grid = (S/128, B*H), block = 128.
// One thread per q-row; q and O accumulator in registers; KV tiles of 32 rows
// in smem; scores staged in padded smem (stride 33 -> conflict-free).
// ---------------------------------------------------------------------------
#define KVT 32

__global__ __launch_bounds__(128) void attn_kernel()
{
    __shared__ float Ks[KVT * DD];        // 8 KB
    __shared__ float Vs[KVT * DD];        // 8 KB
    __shared__ float Sr[128 * (KVT + 1)]; // 16.5 KB, stride 33

    const int tid = threadIdx.x;
    const int qt = blockIdx.x;
    const int bh = blockIdx.y;
    const int qrow = qt * 128 + tid;

    const float4* qg = (const float4*)(g_q + (bh * SS + qrow) * DD);
    float4 q[16];
#pragma unroll
    for (int t = 0; t < 16; ++t) q[t] = qg[t];

    float4 O[16];
#pragma unroll
    for (int t = 0; t < 16; ++t) O[t] = make_float4(0.f, 0.f, 0.f, 0.f);

    float m = -1e30f, l = 0.f;

    const float4* Kg = (const float4*)(g_k + bh * SS * DD);
    const float4* Vg = (const float4*)(g_v + bh * SS * DD);
    float4* Ks4 = (float4*)Ks;
    float4* Vs4 = (float4*)Vs;

    const int ktmax = 4 * qt + 3;   // last kv tile touching this block's rows
    for (int kt = 0; kt <= ktmax; ++kt) {
        // load KV tile: KVT*DD/4 = 512 float4 each, 4 per thread
#pragma unroll
        for (int i = 0; i < 4; ++i) {
            const int idx = tid + i * 128;
            Ks4[idx] = Kg[kt * (KVT * DD / 4) + idx];
            Vs4[idx] = Vg[kt * (KVT * DD / 4) + idx];
        }
        __syncthreads();

        const int jlim = qrow - kt * KVT;   // j <= jlim is unmasked
        float tmax = -1e30f;
#pragma unroll 4
        for (int j = 0; j < KVT; ++j) {
            const float4* kr = Ks4 + j * 16;
            float s0 = 0.f, s1 = 0.f, s2 = 0.f, s3 = 0.f;
#pragma unroll
            for (int t = 0; t < 16; ++t) {
                float4 kv = kr[t];
                s0 = fmaf(q[t].x, kv.x, s0);
                s1 = fmaf(q[t].y, kv.y, s1);
                s2 = fmaf(q[t].z, kv.z, s2);
                s3 = fmaf(q[t].w, kv.w, s3);
            }
            float s = (s0 + s1) + (s2 + s3);
            s = (j <= jlim) ? s : -1e30f;
            Sr[tid * (KVT + 1) + j] = s;
            tmax = fmaxf(tmax, s);
        }

        const float mnew = fmaxf(m, tmax);
        const float corr = __expf(m - mnew);
        l *= corr;
#pragma unroll
        for (int t = 0; t < 16; ++t) {
            O[t].x *= corr; O[t].y *= corr; O[t].z *= corr; O[t].w *= corr;
        }

#pragma unroll 4
        for (int j = 0; j < KVT; ++j) {
            const float p = __expf(Sr[tid * (KVT + 1) + j] - mnew);
            l += p;
            const float4* vr = Vs4 + j * 16;
#pragma unroll
            for (int t = 0; t < 16; ++t) {
                float4 vv = vr[t];
                O[t].x = fmaf(p, vv.x, O[t].x);
                O[t].y = fmaf(p, vv.y, O[t].y);
                O[t].z = fmaf(p, vv.z, O[t].z);
                O[t].w = fmaf(p, vv.w, O[t].w);
            }
        }
        m = mnew;
        __syncthreads();
    }

    const float inv = 1.0f / l;
    const int b = bh >> 4;
    const int h = bh & 15;
    float4* og = (float4*)(g_att + (b * SS + qrow) * EE + h * DD);
#pragma unroll
    for (int t = 0; t < 16; ++t) {
        float4 o;
        o.x = O[t].x * inv; o.y = O[t].y * inv;
        o.z = O[t].z * inv; o.w = O[t].w * inv;
        og[t] = o;
    }
}

// ---------------------------------------------------------------------------
extern "C" void kernel_launch(void* const* d_in, const int* in_sizes, int n_in,
                              void* d_out, int out_size)
{
    const float* x     = (const float*)d_in[0];
    const float* qkv_w = (const float*)d_in[1];
    const float* qkv_b = (const float*)d_in[2];
    const float* out_w = (const float*)d_in[3];
    const float* out_b = (const float*)d_in[4];
    float* out = (float*)d_out;

    // 1) fused QKV projection, scatter to q/k/v in [B,H,S,hd] (q pre-scaled)
    gemm_kernel<0><<<dim3(3072 / 128, MROWS / 128), 256>>>(
        x, qkv_w, qkv_b, nullptr, MROWS, 3 * EE, EE);

    // 2) causal flash attention -> g_att [B,S,E]
    attn_kernel<<<dim3(SS / 128, BB * HH), 128>>>();

    // 3) output projection
    gemm_kernel<1><<<dim3(EE / 128, MROWS / 128), 256>>>(
        nullptr, out_w, out_b, out, MROWS, EE, EE);
}

// round 3
// speedup vs baseline: 1.4244x; 1.4244x over previous
#include <cuda_runtime.h>
#include <cstdint>

#define BB 4
#define SS 2048
#define EE 1024
#define HH 16
#define DD 64
#define MROWS (BB * SS)   // 8192

// Scratch (device globals: allocation-free rule)
__device__ float g_q[BB * HH * SS * DD];    // q pre-scaled by 1/8 (incl. bias)
__device__ float g_k[BB * HH * SS * DD];
__device__ float g_v[BB * HH * SS * DD];
__device__ float g_att[BB * SS * EE];       // attention output, [B,S,E]

// ---------------------------------------------------------------------------
// tf32 helpers (base ISA, works on plain sm_103 target)
// ---------------------------------------------------------------------------
__device__ __forceinline__ uint32_t f2tf32(float f) {
    uint32_t u;
    asm("cvt.rna.tf32.f32 %0, %1;" : "=r"(u) : "f"(f));
    return u;
}

__device__ __forceinline__ void mma8(float* c,
                                     uint32_t a0, uint32_t a1, uint32_t a2, uint32_t a3,
                                     uint32_t b0, uint32_t b1) {
    asm volatile(
        "mma.sync.aligned.m16n8k8.row.col.f32.tf32.tf32.f32 "
        "{%0,%1,%2,%3}, {%4,%5,%6,%7}, {%8,%9}, {%0,%1,%2,%3};"
        : "+f"(c[0]), "+f"(c[1]), "+f"(c[2]), "+f"(c[3])
        : "r"(a0), "r"(a1), "r"(a2), "r"(a3), "r"(b0), "r"(b1));
}

// ===========================================================================
// tf32 mma.sync GEMM: C[M,N] = A[M,K=1024] @ W[N,K]^T + bias
// 128x128 block tile, 8 warps (2x4), 64x32 warp tile, k-chunk 16, dbl buffer.
// MODE 0: A = x, epilogue scatters into g_q/g_k/g_v (q scaled by 1/8)
// MODE 1: A = g_att, epilogue writes Cp with bias
// ===========================================================================
#define LDT 20   // smem row stride in floats (conflict-free: 20r+c spans banks)

template <int MODE>
__global__ __launch_bounds__(256) void gemm_mma(
    const float* __restrict__ Ap, const float* __restrict__ Wp,
    const float* __restrict__ bias, float* __restrict__ Cp, int N)
{
    __shared__ uint32_t As[2][128 * LDT];
    __shared__ uint32_t Bs[2][128 * LDT];

    const float* A = (MODE == 1) ? (const float*)g_att : Ap;
    const int tid = threadIdx.x, lane = tid & 31, wid = tid >> 5;
    const int bm = blockIdx.y, bn = blockIdx.x;
    const int wm = wid >> 2, wn = wid & 3;

    // global staging: each thread 2 float4 per matrix per k-chunk
    const int lr = tid >> 2;        // 0..63
    const int lc = tid & 3;         // float4 col within 16-float chunk
    const float4* Ag = (const float4*)A  + (size_t)(bm * 128 + lr) * 256 + lc;
    const float4* Wg = (const float4*)Wp + (size_t)(bn * 128 + lr) * 256 + lc;

    float acc[4][4][4];
#pragma unroll
    for (int i = 0; i < 4; ++i)
#pragma unroll
        for (int j = 0; j < 4; ++j)
#pragma unroll
            for (int t = 0; t < 4; ++t) acc[i][j][t] = 0.f;

#define STAGE(buf, va0, va1, vb0, vb1)                                        \
    do {                                                                      \
        uint32_t* da = &As[buf][lr * LDT + lc * 4];                           \
        da[0] = f2tf32((va0).x); da[1] = f2tf32((va0).y);                     \
        da[2] = f2tf32((va0).z); da[3] = f2tf32((va0).w);                     \
        uint32_t* da2 = &As[buf][(lr + 64) * LDT + lc * 4];                   \
        da2[0] = f2tf32((va1).x); da2[1] = f2tf32((va1).y);                   \
        da2[2] = f2tf32((va1).z); da2[3] = f2tf32((va1).w);                   \
        uint32_t* db = &Bs[buf][lr * LDT + lc * 4];                           \
        db[0] = f2tf32((vb0).x); db[1] = f2tf32((vb0).y);                     \
        db[2] = f2tf32((vb0).z); db[3] = f2tf32((vb0).w);                     \
        uint32_t* db2 = &Bs[buf][(lr + 64) * LDT + lc * 4];                   \
        db2[0] = f2tf32((vb1).x); db2[1] = f2tf32((vb1).y);                   \
        db2[2] = f2tf32((vb1).z); db2[3] = f2tf32((vb1).w);                   \
    } while (0)

    // preload k-chunk 0
    {
        float4 a0 = Ag[0], a1 = Ag[64 * 256];
        float4 b0 = Wg[0], b1 = Wg[64 * 256];
        STAGE(0, a0, a1, b0, b1);
    }
    __syncthreads();

    const int arow = (lane >> 2);   // 0..7
    const int acol = (lane & 3);    // 0..3

    for (int kt = 0; kt < 64; ++kt) {
        const int cur = kt & 1;
        float4 na0, na1, nb0, nb1;
        if (kt < 63) {
            na0 = Ag[(kt + 1) * 4];
            na1 = Ag[(kt + 1) * 4 + 64 * 256];
            nb0 = Wg[(kt + 1) * 4];
            nb1 = Wg[(kt + 1) * 4 + 64 * 256];
        }
        const uint32_t* as = As[cur];
        const uint32_t* bs = Bs[cur];
#pragma unroll
        for (int kk = 0; kk < 16; kk += 8) {
            uint32_t af[4][4], bf[4][2];
#pragma unroll
            for (int mi = 0; mi < 4; ++mi) {
                const int rb = (wm * 64 + mi * 16 + arow) * LDT + kk + acol;
                af[mi][0] = as[rb];
                af[mi][1] = as[rb + 8 * LDT];
                af[mi][2] = as[rb + 4];
                af[mi][3] = as[rb + 8 * LDT + 4];
            }
#pragma unroll
            for (int ni = 0; ni < 4; ++ni) {
                const int cb = (wn * 32 + ni * 8 + arow) * LDT + kk + acol;
                bf[ni][0] = bs[cb];
                bf[ni][1] = bs[cb + 4];
            }
#pragma unroll
            for (int mi = 0; mi < 4; ++mi)
#pragma unroll
                for (int ni = 0; ni < 4; ++ni)
                    mma8(acc[mi][ni], af[mi][0], af[mi][1], af[mi][2], af[mi][3],
                         bf[ni][0], bf[ni][1]);
        }
        if (kt < 63) {
            STAGE(cur ^ 1, na0, na1, nb0, nb1);
        }
        __syncthreads();
    }
#undef STAGE

    // ---------------- epilogue ----------------
#pragma unroll
    for (int mi = 0; mi < 4; ++mi) {
        const int r0 = bm * 128 + wm * 64 + mi * 16 + arow;
#pragma unroll
        for (int ni = 0; ni < 4; ++ni) {
            const int col = bn * 128 + wn * 32 + ni * 8 + (acol << 1);
            const float bx = bias[col], by = bias[col + 1];
            if (MODE == 1) {
                float2* p0 = (float2*)(Cp + (size_t)r0 * N + col);
                float2* p1 = (float2*)(Cp + (size_t)(r0 + 8) * N + col);
                *p0 = make_float2(acc[mi][ni][0] + bx, acc[mi][ni][1] + by);
                *p1 = make_float2(acc[mi][ni][2] + bx, acc[mi][ni][3] + by);
            } else {
                const int cg = col >> 6;
                const int h = cg / 3, cpart = cg % 3;
                const int d = col & 63;
                const float sc = (cpart == 0) ? 0.125f : 1.0f;
                float* base = (cpart == 0) ? g_q : (cpart == 1) ? g_k : g_v;
#pragma unroll
                for (int rr = 0; rr < 2; ++rr) {
                    const int r = r0 + rr * 8;
                    const int b = r >> 11, s = r & 2047;
                    float2* p = (float2*)(base +
                        (((size_t)(b * HH + h) * SS + s) << 6) + d);
                    *p = make_float2((acc[mi][ni][rr * 2 + 0] + bx) * sc,
                                     (acc[mi][ni][rr * 2 + 1] + by) * sc);
                }
            }
        }
    }
}

// ---------------------------------------------------------------------------
// Flash attention (causal). grid = (S/128, B*H), block = 128. Unchanged.
// ---------------------------------------------------------------------------
#define KVT 32

__global__ __launch_bounds__(128) void attn_kernel()
{
    __shared__ float Ks[KVT * DD];
    __shared__ float Vs[KVT * DD];
    __shared__ float Sr[128 * (KVT + 1)];

    const int tid = threadIdx.x;
    const int qt = blockIdx.x;
    const int bh = blockIdx.y;
    const int qrow = qt * 128 + tid;

    const float4* qg = (const float4*)(g_q + (bh * SS + qrow) * DD);
    float4 q[16];
#pragma unroll
    for (int t = 0; t < 16; ++t) q[t] = qg[t];

    float4 O[16];
#pragma unroll
    for (int t = 0; t < 16; ++t) O[t] = make_float4(0.f, 0.f, 0.f, 0.f);

    float m = -1e30f, l = 0.f;

    const float4* Kg = (const float4*)(g_k + bh * SS * DD);
    const float4* Vg = (const float4*)(g_v + bh * SS * DD);
    float4* Ks4 = (float4*)Ks;
    float4* Vs4 = (float4*)Vs;

    const int ktmax = 4 * qt + 3;
    for (int kt = 0; kt <= ktmax; ++kt) {
#pragma unroll
        for (int i = 0; i < 4; ++i) {
            const int idx = tid + i * 128;
            Ks4[idx] = Kg[kt * (KVT * DD / 4) + idx];
            Vs4[idx] = Vg[kt * (KVT * DD / 4) + idx];
        }
        __syncthreads();

        const int jlim = qrow - kt * KVT;
        float tmax = -1e30f;
#pragma unroll 4
        for (int j = 0; j < KVT; ++j) {
            const float4* kr = Ks4 + j * 16;
            float s0 = 0.f, s1 = 0.f, s2 = 0.f, s3 = 0.f;
#pragma unroll
            for (int t = 0; t < 16; ++t) {
                float4 kv = kr[t];
                s0 = fmaf(q[t].x, kv.x, s0);
                s1 = fmaf(q[t].y, kv.y, s1);
                s2 = fmaf(q[t].z, kv.z, s2);
                s3 = fmaf(q[t].w, kv.w, s3);
            }
            float s = (s0 + s1) + (s2 + s3);
            s = (j <= jlim) ? s : -1e30f;
            Sr[tid * (KVT + 1) + j] = s;
            tmax = fmaxf(tmax, s);
        }

        const float mnew = fmaxf(m, tmax);
        const float corr = __expf(m - mnew);
        l *= corr;
#pragma unroll
        for (int t = 0; t < 16; ++t) {
            O[t].x *= corr; O[t].y *= corr; O[t].z *= corr; O[t].w *= corr;
        }

#pragma unroll 4
        for (int j = 0; j < KVT; ++j) {
            const float p = __expf(Sr[tid * (KVT + 1) + j] - mnew);
            l += p;
            const float4* vr = Vs4 + j * 16;
#pragma unroll
            for (int t = 0; t < 16; ++t) {
                float4 vv = vr[t];
                O[t].x = fmaf(p, vv.x, O[t].x);
                O[t].y = fmaf(p, vv.y, O[t].y);
                O[t].z = fmaf(p, vv.z, O[t].z);
                O[t].w = fmaf(p, vv.w, O[t].w);
            }
        }
        m = mnew;
        __syncthreads();
    }

    const float inv = 1.0f / l;
    const int b = bh >> 4;
    const int h = bh & 15;
    float4* og = (float4*)(g_att + (b * SS + qrow) * EE + h * DD);
#pragma unroll
    for (int t = 0; t < 16; ++t) {
        float4 o;
        o.x = O[t].x * inv; o.y = O[t].y * inv;
        o.z = O[t].z * inv; o.w = O[t].w * inv;
        og[t] = o;
    }
}

// ---------------------------------------------------------------------------
extern "C" void kernel_launch(void* const* d_in, const int* in_sizes, int n_in,
                              void* d_out, int out_size)
{
    const float* x     = (const float*)d_in[0];
    const float* qkv_w = (const float*)d_in[1];
    const float* qkv_b = (const float*)d_in[2];
    const float* out_w = (const float*)d_in[3];
    const float* out_b = (const float*)d_in[4];
    float* out = (float*)d_out;

    // 1) fused QKV projection (tf32 mma.sync) -> g_q/g_k/g_v [B,H,S,hd]
    gemm_mma<0><<<dim3(3072 / 128, MROWS / 128), 256>>>(
        x, qkv_w, qkv_b, nullptr, 3 * EE);

    // 2) causal flash attention -> g_att [B,S,E]
    attn_kernel<<<dim3(SS / 128, BB * HH), 128>>>();

    // 3) output projection (tf32 mma.sync)
    gemm_mma<1><<<dim3(EE / 128, MROWS / 128), 256>>>(
        nullptr, out_w, out_b, out, EE);
}

// round 4
// speedup vs baseline: 2.4173x; 1.6970x over previous
#include <cuda_runtime.h>
#include <cstdint>

#define BB 4
#define SS 2048
#define EE 1024
#define HH 16
#define DD 64
#define MROWS (BB * SS)   // 8192
#define L2E 1.4426950408889634f

// Scratch (device globals: allocation-free rule)
__device__ float g_q[BB * HH * SS * DD];    // q pre-scaled by 1/8 (incl. bias)
__device__ float g_k[BB * HH * SS * DD];
__device__ float g_v[BB * HH * SS * DD];
__device__ float g_att[BB * SS * EE];       // attention output, [B,S,E]

// ---------------------------------------------------------------------------
// tf32 helpers (base ISA, works on plain sm_103 target)
// ---------------------------------------------------------------------------
__device__ __forceinline__ uint32_t f2tf32(float f) {
    uint32_t u;
    asm("cvt.rna.tf32.f32 %0, %1;" : "=r"(u) : "f"(f));
    return u;
}

__device__ __forceinline__ void mma8(float* c,
                                     uint32_t a0, uint32_t a1, uint32_t a2, uint32_t a3,
                                     uint32_t b0, uint32_t b1) {
    asm volatile(
        "mma.sync.aligned.m16n8k8.row.col.f32.tf32.tf32.f32 "
        "{%0,%1,%2,%3}, {%4,%5,%6,%7}, {%8,%9}, {%0,%1,%2,%3};"
        : "+f"(c[0]), "+f"(c[1]), "+f"(c[2]), "+f"(c[3])
        : "r"(a0), "r"(a1), "r"(a2), "r"(a3), "r"(b0), "r"(b1));
}

// fast exp2: round-to-nearest range reduction, deg-4 Taylor on [-0.5, 0.5]
// rel err <= ~4e-5; runs on fma/alu pipes (no MUFU bottleneck)
__device__ __forceinline__ float fexp2(float x) {
    x = fmaxf(x, -125.0f);
    const int ei = __float2int_rn(x);
    const float f = x - (float)ei;
    float p = fmaf(f, 0.0096181291f, 0.0555041087f);
    p = fmaf(f, p, 0.2402264923f);
    p = fmaf(f, p, 0.6931471806f);
    p = fmaf(f, p, 1.0f);
    return p * __int_as_float((ei + 127) << 23);
}

// ===========================================================================
// tf32 mma.sync GEMM (unchanged from R3): C = A @ W^T + bias
// ===========================================================================
#define LDT 20

template <int MODE>
__global__ __launch_bounds__(256) void gemm_mma(
    const float* __restrict__ Ap, const float* __restrict__ Wp,
    const float* __restrict__ bias, float* __restrict__ Cp, int N)
{
    __shared__ uint32_t As[2][128 * LDT];
    __shared__ uint32_t Bs[2][128 * LDT];

    const float* A = (MODE == 1) ? (const float*)g_att : Ap;
    const int tid = threadIdx.x, lane = tid & 31, wid = tid >> 5;
    const int bm = blockIdx.y, bn = blockIdx.x;
    const int wm = wid >> 2, wn = wid & 3;

    const int lr = tid >> 2;
    const int lc = tid & 3;
    const float4* Ag = (const float4*)A  + (size_t)(bm * 128 + lr) * 256 + lc;
    const float4* Wg = (const float4*)Wp + (size_t)(bn * 128 + lr) * 256 + lc;

    float acc[4][4][4];
#pragma unroll
    for (int i = 0; i < 4; ++i)
#pragma unroll
        for (int j = 0; j < 4; ++j)
#pragma unroll
            for (int t = 0; t < 4; ++t) acc[i][j][t] = 0.f;

#define STAGE(buf, va0, va1, vb0, vb1)                                        \
    do {                                                                      \
        uint32_t* da = &As[buf][lr * LDT + lc * 4];                           \
        da[0] = f2tf32((va0).x); da[1] = f2tf32((va0).y);                     \
        da[2] = f2tf32((va0).z); da[3] = f2tf32((va0).w);                     \
        uint32_t* da2 = &As[buf][(lr + 64) * LDT + lc * 4];                   \
        da2[0] = f2tf32((va1).x); da2[1] = f2tf32((va1).y);                   \
        da2[2] = f2tf32((va1).z); da2[3] = f2tf32((va1).w);                   \
        uint32_t* db = &Bs[buf][lr * LDT + lc * 4];                           \
        db[0] = f2tf32((vb0).x); db[1] = f2tf32((vb0).y);                     \
        db[2] = f2tf32((vb0).z); db[3] = f2tf32((vb0).w);                     \
        uint32_t* db2 = &Bs[buf][(lr + 64) * LDT + lc * 4];                   \
        db2[0] = f2tf32((vb1).x); db2[1] = f2tf32((vb1).y);                   \
        db2[2] = f2tf32((vb1).z); db2[3] = f2tf32((vb1).w);                   \
    } while (0)

    {
        float4 a0 = Ag[0], a1 = Ag[64 * 256];
        float4 b0 = Wg[0], b1 = Wg[64 * 256];
        STAGE(0, a0, a1, b0, b1);
    }
    __syncthreads();

    const int arow = (lane >> 2);
    const int acol = (lane & 3);

    for (int kt = 0; kt < 64; ++kt) {
        const int cur = kt & 1;
        float4 na0, na1, nb0, nb1;
        if (kt < 63) {
            na0 = Ag[(kt + 1) * 4];
            na1 = Ag[(kt + 1) * 4 + 64 * 256];
            nb0 = Wg[(kt + 1) * 4];
            nb1 = Wg[(kt + 1) * 4 + 64 * 256];
        }
        const uint32_t* as = As[cur];
        const uint32_t* bs = Bs[cur];
#pragma unroll
        for (int kk = 0; kk < 16; kk += 8) {
            uint32_t af[4][4], bf[4][2];
#pragma unroll
            for (int mi = 0; mi < 4; ++mi) {
                const int rb = (wm * 64 + mi * 16 + arow) * LDT + kk + acol;
                af[mi][0] = as[rb];
                af[mi][1] = as[rb + 8 * LDT];
                af[mi][2] = as[rb + 4];
                af[mi][3] = as[rb + 8 * LDT + 4];
            }
#pragma unroll
            for (int ni = 0; ni < 4; ++ni) {
                const int cb = (wn * 32 + ni * 8 + arow) * LDT + kk + acol;
                bf[ni][0] = bs[cb];
                bf[ni][1] = bs[cb + 4];
            }
#pragma unroll
            for (int mi = 0; mi < 4; ++mi)
#pragma unroll
                for (int ni = 0; ni < 4; ++ni)
                    mma8(acc[mi][ni], af[mi][0], af[mi][1], af[mi][2], af[mi][3],
                         bf[ni][0], bf[ni][1]);
        }
        if (kt < 63) {
            STAGE(cur ^ 1, na0, na1, nb0, nb1);
        }
        __syncthreads();
    }
#undef STAGE

#pragma unroll
    for (int mi = 0; mi < 4; ++mi) {
        const int r0 = bm * 128 + wm * 64 + mi * 16 + arow;
#pragma unroll
        for (int ni = 0; ni < 4; ++ni) {
            const int col = bn * 128 + wn * 32 + ni * 8 + (acol << 1);
            const float bx = bias[col], by = bias[col + 1];
            if (MODE == 1) {
                float2* p0 = (float2*)(Cp + (size_t)r0 * N + col);
                float2* p1 = (float2*)(Cp + (size_t)(r0 + 8) * N + col);
                *p0 = make_float2(acc[mi][ni][0] + bx, acc[mi][ni][1] + by);
                *p1 = make_float2(acc[mi][ni][2] + bx, acc[mi][ni][3] + by);
            } else {
                const int cg = col >> 6;
                const int h = cg / 3, cpart = cg % 3;
                const int d = col & 63;
                const float sc = (cpart == 0) ? 0.125f : 1.0f;
                float* base = (cpart == 0) ? g_q : (cpart == 1) ? g_k : g_v;
#pragma unroll
                for (int rr = 0; rr < 2; ++rr) {
                    const int r = r0 + rr * 8;
                    const int b = r >> 11, s = r & 2047;
                    float2* p = (float2*)(base +
                        (((size_t)(b * HH + h) * SS + s) << 6) + d);
                    *p = make_float2((acc[mi][ni][rr * 2 + 0] + bx) * sc,
                                     (acc[mi][ni][rr * 2 + 1] + by) * sc);
                }
            }
        }
    }
}

// ===========================================================================
// Tensor-core causal flash attention.
// grid = (S/128, B*H), block = 128 (4 warps x m32 warp tile), KV tile 64.
// QK^T: A = Q frags (gmem/L1), B = K smem split hi+lo tf32 (2 MMAs).
// softmax in C fragments (quad shfl + poly exp2), P -> warp-private smem,
// PV: A = P smem, B = Vt smem (V transposed at copy). Online flash update.
// Dynamic smem: Khi/Klo/Vt 64x68 + P 4x32x68 = 87040 B -> 2 CTA/SM.
// ===========================================================================
#define ATTN_SMEM 87040

__global__ __launch_bounds__(128, 2) void attn_mma()
{
    extern __shared__ uint32_t smm[];
    uint32_t* Khi = smm;                    // [64][68]
    uint32_t* Klo = smm + 4352;
    uint32_t* Vt  = smm + 8704;             // [d=64][kv stride 68]
    const int tid = threadIdx.x, lane = tid & 31, wid = tid >> 5;
    uint32_t* Pw  = smm + 13056 + wid * 2176;   // [32][68] per warp
    const int gr = lane >> 2, tc = lane & 3;
    const int bh = blockIdx.y, qt = blockIdx.x;
    const int qbase = qt * 128;
    const int wrow = qbase + wid * 32;

    const float*  Qb = g_q + ((size_t)bh * SS + wrow) * DD;
    const float4* K4 = (const float4*)(g_k + (size_t)bh * SS * DD);
    const float4* V4 = (const float4*)(g_v + (size_t)bh * SS * DD);

    float Oc[2][8][4];
#pragma unroll
    for (int mi = 0; mi < 2; ++mi)
#pragma unroll
        for (int ni = 0; ni < 8; ++ni)
#pragma unroll
            for (int r = 0; r < 4; ++r) Oc[mi][ni][r] = 0.f;
    float mrow[2][2] = {{-1e30f, -1e30f}, {-1e30f, -1e30f}};
    float lrow[2][2] = {{0.f, 0.f}, {0.f, 0.f}};

    const int nkt = 2 * qt + 2;
    for (int kt = 0; kt < nkt; ++kt) {
        const int kvb = kt * 64;
        __syncthreads();

        // ---- cooperative copy: K (hi/lo tf32) + V transposed ----
#pragma unroll
        for (int h = 0; h < 2; ++h) {
            float4 kr[4], vr[4];
#pragma unroll
            for (int j = 0; j < 4; ++j) {
                const int i = tid + (h * 4 + j) * 128;
                kr[j] = K4[kvb * 16 + i];
                vr[j] = V4[kvb * 16 + i];
            }
#pragma unroll
            for (int j = 0; j < 4; ++j) {
                const int i = tid + (h * 4 + j) * 128;
                const int r = i >> 4, c4 = i & 15;
                uint4 hi, lo;
                hi.x = f2tf32(kr[j].x); lo.x = f2tf32(kr[j].x - __uint_as_float(hi.x));
                hi.y = f2tf32(kr[j].y); lo.y = f2tf32(kr[j].y - __uint_as_float(hi.y));
                hi.z = f2tf32(kr[j].z); lo.z = f2tf32(kr[j].z - __uint_as_float(hi.z));
                hi.w = f2tf32(kr[j].w); lo.w = f2tf32(kr[j].w - __uint_as_float(hi.w));
                *(uint4*)(Khi + r * 68 + c4 * 4) = hi;
                *(uint4*)(Klo + r * 68 + c4 * 4) = lo;
                Vt[(c4 * 4 + 0) * 68 + r] = f2tf32(vr[j].x);
                Vt[(c4 * 4 + 1) * 68 + r] = f2tf32(vr[j].y);
                Vt[(c4 * 4 + 2) * 68 + r] = f2tf32(vr[j].z);
                Vt[(c4 * 4 + 3) * 68 + r] = f2tf32(vr[j].w);
            }
        }
        __syncthreads();

        if (kvb > wrow + 31) continue;   // this warp fully masked (last tile)

        // ---- QK^T: sc[m32][kv64], K split hi+lo ----
        float sc[2][8][4];
#pragma unroll
        for (int mi = 0; mi < 2; ++mi)
#pragma unroll
            for (int ni = 0; ni < 8; ++ni)
#pragma unroll
                for (int r = 0; r < 4; ++r) sc[mi][ni][r] = 0.f;

#pragma unroll
        for (int kk = 0; kk < 8; ++kk) {
            uint32_t qa[2][4];
#pragma unroll
            for (int mi = 0; mi < 2; ++mi) {
                const float* qp = Qb + (mi * 16 + gr) * DD + kk * 8 + tc;
                qa[mi][0] = f2tf32(qp[0]);
                qa[mi][1] = f2tf32(qp[8 * DD]);
                qa[mi][2] = f2tf32(qp[4]);
                qa[mi][3] = f2tf32(qp[8 * DD + 4]);
            }
            uint32_t bhv[8][2], blv[8][2];
#pragma unroll
            for (int ni = 0; ni < 8; ++ni) {
                const int ba = (ni * 8 + gr) * 68 + kk * 8 + tc;
                bhv[ni][0] = Khi[ba]; bhv[ni][1] = Khi[ba + 4];
                blv[ni][0] = Klo[ba]; blv[ni][1] = Klo[ba + 4];
            }
#pragma unroll
            for (int mi = 0; mi < 2; ++mi)
#pragma unroll
                for (int ni = 0; ni < 8; ++ni) {
                    mma8(sc[mi][ni], qa[mi][0], qa[mi][1], qa[mi][2], qa[mi][3],
                         bhv[ni][0], bhv[ni][1]);
                    mma8(sc[mi][ni], qa[mi][0], qa[mi][1], qa[mi][2], qa[mi][3],
                         blv[ni][0], blv[ni][1]);
                }
        }

        // ---- causal mask (only diagonal-region tiles) ----
        if (kvb + 63 > qbase) {
#pragma unroll
            for (int mi = 0; mi < 2; ++mi)
#pragma unroll
                for (int ni = 0; ni < 8; ++ni)
#pragma unroll
                    for (int r = 0; r < 4; ++r) {
                        const int i = wrow + mi * 16 + gr + (r >> 1) * 8;
                        const int j = kvb + ni * 8 + 2 * tc + (r & 1);
                        if (j > i) sc[mi][ni][r] = -1e30f;
                    }
        }

        // ---- online softmax in fragments ----
#pragma unroll
        for (int mi = 0; mi < 2; ++mi)
#pragma unroll
            for (int rr = 0; rr < 2; ++rr) {
                float mx = -1e30f;
#pragma unroll
                for (int ni = 0; ni < 8; ++ni)
                    mx = fmaxf(mx, fmaxf(sc[mi][ni][rr * 2], sc[mi][ni][rr * 2 + 1]));
                mx = fmaxf(mx, __shfl_xor_sync(0xffffffffu, mx, 1));
                mx = fmaxf(mx, __shfl_xor_sync(0xffffffffu, mx, 2));
                const float mnew = fmaxf(mrow[mi][rr], mx);
                const float corr = fexp2((mrow[mi][rr] - mnew) * L2E);
                mrow[mi][rr] = mnew;
                const float mL = mnew * L2E;
                float rs = 0.f;
#pragma unroll
                for (int ni = 0; ni < 8; ++ni) {
                    const float p0 = fexp2(fmaf(sc[mi][ni][rr * 2],     L2E, -mL));
                    const float p1 = fexp2(fmaf(sc[mi][ni][rr * 2 + 1], L2E, -mL));
                    rs += p0 + p1;
                    Oc[mi][ni][rr * 2]     *= corr;
                    Oc[mi][ni][rr * 2 + 1] *= corr;
                    uint2 pp;
                    pp.x = f2tf32(p0);
                    pp.y = f2tf32(p1);
                    *(uint2*)(Pw + (mi * 16 + rr * 8 + gr) * 68 + ni * 8 + 2 * tc) = pp;
                }
                rs += __shfl_xor_sync(0xffffffffu, rs, 1);
                rs += __shfl_xor_sync(0xffffffffu, rs, 2);
                lrow[mi][rr] = lrow[mi][rr] * corr + rs;
            }
        __syncwarp();

        // ---- PV: Oc += P @ V ----
#pragma unroll
        for (int kk = 0; kk < 8; ++kk) {
            uint32_t pf[2][4], vfv[8][2];
#pragma unroll
            for (int mi = 0; mi < 2; ++mi) {
                const int pa = (mi * 16 + gr) * 68 + kk * 8 + tc;
                pf[mi][0] = Pw[pa];
                pf[mi][1] = Pw[pa + 8 * 68];
                pf[mi][2] = Pw[pa + 4];
                pf[mi][3] = Pw[pa + 8 * 68 + 4];
            }
#pragma unroll
            for (int ni = 0; ni < 8; ++ni) {
                const int va = (ni * 8 + gr) * 68 + kk * 8 + tc;
                vfv[ni][0] = Vt[va]; vfv[ni][1] = Vt[va + 4];
            }
#pragma unroll
            for (int mi = 0; mi < 2; ++mi)
#pragma unroll
                for (int ni = 0; ni < 8; ++ni)
                    mma8(Oc[mi][ni], pf[mi][0], pf[mi][1], pf[mi][2], pf[mi][3],
                         vfv[ni][0], vfv[ni][1]);
        }
    }

    // ---- normalize + store to g_att [B,S,E] ----
    const int b = bh >> 4, hh = bh & 15;
#pragma unroll
    for (int mi = 0; mi < 2; ++mi)
#pragma unroll
        for (int rr = 0; rr < 2; ++rr) {
            const float inv = 1.0f / lrow[mi][rr];
            const int row = wrow + mi * 16 + rr * 8 + gr;
            float* og = g_att + (size_t)(b * SS + row) * EE + hh * 64;
#pragma unroll
            for (int ni = 0; ni < 8; ++ni) {
                float2 o;
                o.x = Oc[mi][ni][rr * 2]     * inv;
                o.y = Oc[mi][ni][rr * 2 + 1] * inv;
                *(float2*)(og + ni * 8 + 2 * tc) = o;
            }
        }
}

// ---------------------------------------------------------------------------
extern "C" void kernel_launch(void* const* d_in, const int* in_sizes, int n_in,
                              void* d_out, int out_size)
{
    const float* x     = (const float*)d_in[0];
    const float* qkv_w = (const float*)d_in[1];
    const float* qkv_b = (const float*)d_in[2];
    const float* out_w = (const float*)d_in[3];
    const float* out_b = (const float*)d_in[4];
    float* out = (float*)d_out;

    cudaFuncSetAttribute(attn_mma, cudaFuncAttributeMaxDynamicSharedMemorySize,
                         ATTN_SMEM);

    // 1) fused QKV projection (tf32 mma.sync) -> g_q/g_k/g_v [B,H,S,hd]
    gemm_mma<0><<<dim3(3072 / 128, MROWS / 128), 256>>>(
        x, qkv_w, qkv_b, nullptr, 3 * EE);

    // 2) causal flash attention (tf32 mma.sync) -> g_att [B,S,E]
    attn_mma<<<dim3(SS / 128, BB * HH), 128, ATTN_SMEM>>>();

    // 3) output projection (tf32 mma.sync)
    gemm_mma<1><<<dim3(EE / 128, MROWS / 128), 256>>>(
        nullptr, out_w, out_b, out, EE);
}

// round 5
// speedup vs baseline: 2.5183x; 1.0418x over previous
#include <cuda_runtime.h>
#include <cstdint>

#define BB 4
#define SS 2048
#define EE 1024
#define HH 16
#define DD 64
#define MROWS (BB * SS)   // 8192
#define L2E 1.4426950408889634f

// Scratch (device globals: allocation-free rule)
__device__ float g_q[BB * HH * SS * DD];    // tf32-rounded, scaled by 1/8, +bias
__device__ float g_khi[BB * HH * SS * DD];  // tf32 hi part of k (+bias)
__device__ float g_klo[BB * HH * SS * DD];  // tf32 lo part of k
__device__ float g_v[BB * HH * SS * DD];    // tf32-rounded v (+bias)
__device__ float g_att[BB * SS * EE];       // attention output, [B,S,E]

// ---------------------------------------------------------------------------
__device__ __forceinline__ uint32_t f2tf32(float f) {
    uint32_t u;
    asm("cvt.rna.tf32.f32 %0, %1;" : "=r"(u) : "f"(f));
    return u;
}

__device__ __forceinline__ void mma8(float* c,
                                     uint32_t a0, uint32_t a1, uint32_t a2, uint32_t a3,
                                     uint32_t b0, uint32_t b1) {
    asm volatile(
        "mma.sync.aligned.m16n8k8.row.col.f32.tf32.tf32.f32 "
        "{%0,%1,%2,%3}, {%4,%5,%6,%7}, {%8,%9}, {%0,%1,%2,%3};"
        : "+f"(c[0]), "+f"(c[1]), "+f"(c[2]), "+f"(c[3])
        : "r"(a0), "r"(a1), "r"(a2), "r"(a3), "r"(b0), "r"(b1));
}

// fast exp2 on fma pipe (no MUFU bottleneck)
__device__ __forceinline__ float fexp2(float x) {
    x = fmaxf(x, -125.0f);
    const int ei = __float2int_rn(x);
    const float f = x - (float)ei;
    float p = fmaf(f, 0.0096181291f, 0.0555041087f);
    p = fmaf(f, p, 0.2402264923f);
    p = fmaf(f, p, 0.6931471806f);
    p = fmaf(f, p, 1.0f);
    return p * __int_as_float((ei + 127) << 23);
}

// ===========================================================================
// tf32 mma.sync GEMM: C[M,N] = A[M,K=1024] @ W[N,K]^T + bias
// CTA tile 128x256, 8 warps (2x4) of 64x64 warp tiles, k-chunk 16, dbl buffer.
// MODE 0: A = x, epilogue -> g_q (tf32,scaled) / g_khi+g_klo / g_v (tf32)
// MODE 1: A = g_att, epilogue writes Cp with bias
// ===========================================================================
#define LDT 20
#define ASZ (128 * LDT)                 // one A buffer (uint32 words)
#define BSZ (256 * LDT)
#define GEMM_SMEM ((2 * ASZ + 2 * BSZ) * 4)   // 61440 B

template <int MODE>
__global__ __launch_bounds__(256, 1) void gemm_mma(
    const float* __restrict__ Ap, const float* __restrict__ Wp,
    const float* __restrict__ bias, float* __restrict__ Cp, int N)
{
    extern __shared__ uint32_t sm[];
    uint32_t* As = sm;                  // [2][128*LDT]
    uint32_t* Bs = sm + 2 * ASZ;        // [2][256*LDT]

    const float* A = (MODE == 1) ? (const float*)g_att : Ap;
    const int tid = threadIdx.x, lane = tid & 31, wid = tid >> 5;
    const int bm = blockIdx.y, bn = blockIdx.x;
    const int wm = wid >> 2, wn = wid & 3;        // 2 x 4 warp grid
    const int gr = lane >> 2, tc = lane & 3;

    // staging indices
    const int rA = (tid + 0) >> 2;                // with +256: rows f>>2
    const int cA = tid & 3;
    const float4* Ag = (const float4*)A  + (size_t)(bm * 128) * 256;
    const float4* Wg = (const float4*)Wp + (size_t)(bn * 256) * 256;

    float acc[4][8][4];
#pragma unroll
    for (int i = 0; i < 4; ++i)
#pragma unroll
        for (int j = 0; j < 8; ++j)
#pragma unroll
            for (int t = 0; t < 4; ++t) acc[i][j][t] = 0.f;

#define STAGE(buf, va, vb)                                                    \
    do {                                                                      \
        _Pragma("unroll")                                                     \
        for (int t = 0; t < 2; ++t) {                                         \
            const int f = tid + t * 256;                                      \
            uint32_t* d = &As[(buf) * ASZ + (f >> 2) * LDT + (f & 3) * 4];    \
            d[0] = f2tf32(va[t].x); d[1] = f2tf32(va[t].y);                   \
            d[2] = f2tf32(va[t].z); d[3] = f2tf32(va[t].w);                   \
        }                                                                     \
        _Pragma("unroll")                                                     \
        for (int t = 0; t < 4; ++t) {                                         \
            const int f = tid + t * 256;                                      \
            uint32_t* d = &Bs[(buf) * BSZ + (f >> 2) * LDT + (f & 3) * 4];    \
            d[0] = f2tf32(vb[t].x); d[1] = f2tf32(vb[t].y);                   \
            d[2] = f2tf32(vb[t].z); d[3] = f2tf32(vb[t].w);                   \
        }                                                                     \
    } while (0)

#define FETCH(kt, va, vb)                                                     \
    do {                                                                      \
        _Pragma("unroll")                                                     \
        for (int t = 0; t < 2; ++t) {                                         \
            const int f = tid + t * 256;                                      \
            va[t] = Ag[(size_t)(f >> 2) * 256 + (kt) * 4 + (f & 3)];          \
        }                                                                     \
        _Pragma("unroll")                                                     \
        for (int t = 0; t < 4; ++t) {                                         \
            const int f = tid + t * 256;                                      \
            vb[t] = Wg[(size_t)(f >> 2) * 256 + (kt) * 4 + (f & 3)];          \
        }                                                                     \
    } while (0)

    {
        float4 va[2], vb[4];
        FETCH(0, va, vb);
        STAGE(0, va, vb);
    }
    __syncthreads();

    for (int kt = 0; kt < 64; ++kt) {
        const int cur = kt & 1;
        float4 va[2], vb[4];
        if (kt < 63) FETCH(kt + 1, va, vb);

        const uint32_t* as = As + cur * ASZ;
        const uint32_t* bs = Bs + cur * BSZ;
#pragma unroll
        for (int kk = 0; kk < 16; kk += 8) {
            uint32_t af[4][4], bf[8][2];
#pragma unroll
            for (int mi = 0; mi < 4; ++mi) {
                const int rb = (wm * 64 + mi * 16 + gr) * LDT + kk + tc;
                af[mi][0] = as[rb];
                af[mi][1] = as[rb + 8 * LDT];
                af[mi][2] = as[rb + 4];
                af[mi][3] = as[rb + 8 * LDT + 4];
            }
#pragma unroll
            for (int ni = 0; ni < 8; ++ni) {
                const int cb = (wn * 64 + ni * 8 + gr) * LDT + kk + tc;
                bf[ni][0] = bs[cb];
                bf[ni][1] = bs[cb + 4];
            }
#pragma unroll
            for (int mi = 0; mi < 4; ++mi)
#pragma unroll
                for (int ni = 0; ni < 8; ++ni)
                    mma8(acc[mi][ni], af[mi][0], af[mi][1], af[mi][2], af[mi][3],
                         bf[ni][0], bf[ni][1]);
        }
        if (kt < 63) STAGE(cur ^ 1, va, vb);
        __syncthreads();
    }
#undef STAGE
#undef FETCH

    // ---------------- epilogue ----------------
    if (MODE == 1) {
#pragma unroll
        for (int mi = 0; mi < 4; ++mi)
#pragma unroll
            for (int rr = 0; rr < 2; ++rr) {
                const int row = bm * 128 + wm * 64 + mi * 16 + rr * 8 + gr;
#pragma unroll
                for (int ni = 0; ni < 8; ++ni) {
                    const int col = bn * 256 + wn * 64 + ni * 8 + 2 * tc;
                    float2 o;
                    o.x = acc[mi][ni][rr * 2]     + bias[col];
                    o.y = acc[mi][ni][rr * 2 + 1] + bias[col + 1];
                    *(float2*)(Cp + (size_t)row * N + col) = o;
                }
            }
    } else {
        // this warp's 64 cols = one (head, part) group exactly
        const int cgw = bn * 4 + wn;            // 0..47
        const int h = cgw / 3, cpart = cgw % 3;
        float* dstb = (cpart == 0) ? g_q : (cpart == 1) ? g_khi : g_v;
#pragma unroll
        for (int mi = 0; mi < 4; ++mi)
#pragma unroll
            for (int rr = 0; rr < 2; ++rr) {
                const int row = bm * 128 + wm * 64 + mi * 16 + rr * 8 + gr;
                const int b = row >> 11, s = row & 2047;
                const size_t ro = ((size_t)(b * HH + h) * SS + s) << 6;
#pragma unroll
                for (int ni = 0; ni < 8; ++ni) {
                    const int col = bn * 256 + wn * 64 + ni * 8 + 2 * tc;
                    const int d = ni * 8 + 2 * tc;
                    float v0 = acc[mi][ni][rr * 2]     + bias[col];
                    float v1 = acc[mi][ni][rr * 2 + 1] + bias[col + 1];
                    if (cpart == 0) { v0 *= 0.125f; v1 *= 0.125f; }
                    const uint32_t h0 = f2tf32(v0), h1 = f2tf32(v1);
                    float2 o;
                    o.x = __uint_as_float(h0);
                    o.y = __uint_as_float(h1);
                    *(float2*)(dstb + ro + d) = o;
                    if (cpart == 1) {
                        float2 lo;
                        lo.x = __uint_as_float(f2tf32(v0 - __uint_as_float(h0)));
                        lo.y = __uint_as_float(f2tf32(v1 - __uint_as_float(h1)));
                        *(float2*)(g_klo + ro + d) = lo;
                    }
                }
            }
    }
}

// ===========================================================================
// Tensor-core causal flash attention.
// grid = (S/128, B*H), block = 128 (4 warps x m32), KV tile 64.
// K pre-split hi/lo tf32 in gmem; V pre-rounded, kept NATURAL [kv][d] in smem
// (stride 72 -> conflict-free transposed fragment reads, no transpose stores).
// Q pre-rounded tf32 in g_q -> raw uint A-fragments.
// ===========================================================================
#define VST 72
#define ATTN_SMEM ((4352 + 4352 + 64 * VST + 4 * 2176) * 4)   // 88064 B

__global__ __launch_bounds__(128, 2) void attn_mma()
{
    extern __shared__ uint32_t smm[];
    uint32_t* Khi = smm;                        // [64][68]
    uint32_t* Klo = smm + 4352;                 // [64][68]
    uint32_t* Vs  = smm + 8704;                 // [64][VST] natural layout
    const int tid = threadIdx.x, lane = tid & 31, wid = tid >> 5;
    uint32_t* Pw  = smm + 8704 + 64 * VST + wid * 2176;   // [32][68] per warp
    const int gr = lane >> 2, tc = lane & 3;
    const int bh = blockIdx.y, qt = blockIdx.x;
    const int qbase = qt * 128;
    const int wrow = qbase + wid * 32;

    const float* Qb  = g_q + ((size_t)bh * SS + wrow) * DD;
    const uint4* KH4 = (const uint4*)(g_khi + (size_t)bh * SS * DD);
    const uint4* KL4 = (const uint4*)(g_klo + (size_t)bh * SS * DD);
    const uint4* V4  = (const uint4*)(g_v   + (size_t)bh * SS * DD);

    float Oc[2][8][4];
#pragma unroll
    for (int mi = 0; mi < 2; ++mi)
#pragma unroll
        for (int ni = 0; ni < 8; ++ni)
#pragma unroll
            for (int r = 0; r < 4; ++r) Oc[mi][ni][r] = 0.f;
    float mrow[2][2] = {{-1e30f, -1e30f}, {-1e30f, -1e30f}};
    float lrow[2][2] = {{0.f, 0.f}, {0.f, 0.f}};

    const int nkt = 2 * qt + 2;
    for (int kt = 0; kt < nkt; ++kt) {
        const int kvb = kt * 64;
        __syncthreads();

        // ---- cooperative copy: pure data movement, all STS.128 ----
#pragma unroll
        for (int j = 0; j < 8; ++j) {
            const int f = tid + j * 128;           // 0..1023
            const int r = f >> 4, c4 = f & 15;
            *(uint4*)(Khi + r * 68 + c4 * 4) = KH4[kvb * 16 + f];
            *(uint4*)(Klo + r * 68 + c4 * 4) = KL4[kvb * 16 + f];
            *(uint4*)(Vs + r * VST + c4 * 4) = V4[kvb * 16 + f];
        }
        __syncthreads();

        if (kvb > wrow + 31) continue;   // warp fully masked (last tile)

        // ---- QK^T: sc[m32][kv64], K split hi+lo ----
        float sc[2][8][4];
#pragma unroll
        for (int mi = 0; mi < 2; ++mi)
#pragma unroll
            for (int ni = 0; ni < 8; ++ni)
#pragma unroll
                for (int r = 0; r < 4; ++r) sc[mi][ni][r] = 0.f;

#pragma unroll
        for (int kk = 0; kk < 8; ++kk) {
            uint32_t qa[2][4];
#pragma unroll
            for (int mi = 0; mi < 2; ++mi) {
                const float* qp = Qb + (mi * 16 + gr) * DD + kk * 8 + tc;
                qa[mi][0] = __float_as_uint(qp[0]);
                qa[mi][1] = __float_as_uint(qp[8 * DD]);
                qa[mi][2] = __float_as_uint(qp[4]);
                qa[mi][3] = __float_as_uint(qp[8 * DD + 4]);
            }
            uint32_t bhv[8][2], blv[8][2];
#pragma unroll
            for (int ni = 0; ni < 8; ++ni) {
                const int ba = (ni * 8 + gr) * 68 + kk * 8 + tc;
                bhv[ni][0] = Khi[ba]; bhv[ni][1] = Khi[ba + 4];
                blv[ni][0] = Klo[ba]; blv[ni][1] = Klo[ba + 4];
            }
#pragma unroll
            for (int mi = 0; mi < 2; ++mi)
#pragma unroll
                for (int ni = 0; ni < 8; ++ni) {
                    mma8(sc[mi][ni], qa[mi][0], qa[mi][1], qa[mi][2], qa[mi][3],
                         bhv[ni][0], bhv[ni][1]);
                    mma8(sc[mi][ni], qa[mi][0], qa[mi][1], qa[mi][2], qa[mi][3],
                         blv[ni][0], blv[ni][1]);
                }
        }

        // ---- causal mask ----
        if (kvb + 63 > qbase) {
#pragma unroll
            for (int mi = 0; mi < 2; ++mi)
#pragma unroll
                for (int ni = 0; ni < 8; ++ni)
#pragma unroll
                    for (int r = 0; r < 4; ++r) {
                        const int i = wrow + mi * 16 + gr + (r >> 1) * 8;
                        const int j = kvb + ni * 8 + 2 * tc + (r & 1);
                        if (j > i) sc[mi][ni][r] = -1e30f;
                    }
        }

        // ---- online softmax in fragments ----
#pragma unroll
        for (int mi = 0; mi < 2; ++mi)
#pragma unroll
            for (int rr = 0; rr < 2; ++rr) {
                float mx = -1e30f;
#pragma unroll
                for (int ni = 0; ni < 8; ++ni)
                    mx = fmaxf(mx, fmaxf(sc[mi][ni][rr * 2], sc[mi][ni][rr * 2 + 1]));
                mx = fmaxf(mx, __shfl_xor_sync(0xffffffffu, mx, 1));
                mx = fmaxf(mx, __shfl_xor_sync(0xffffffffu, mx, 2));
                const float mnew = fmaxf(mrow[mi][rr], mx);
                const float corr = fexp2((mrow[mi][rr] - mnew) * L2E);
                mrow[mi][rr] = mnew;
                const float mL = mnew * L2E;
                float rs = 0.f;
#pragma unroll
                for (int ni = 0; ni < 8; ++ni) {
                    const float p0 = fexp2(fmaf(sc[mi][ni][rr * 2],     L2E, -mL));
                    const float p1 = fexp2(fmaf(sc[mi][ni][rr * 2 + 1], L2E, -mL));
                    rs += p0 + p1;
                    Oc[mi][ni][rr * 2]     *= corr;
                    Oc[mi][ni][rr * 2 + 1] *= corr;
                    uint2 pp;
                    pp.x = f2tf32(p0);
                    pp.y = f2tf32(p1);
                    *(uint2*)(Pw + (mi * 16 + rr * 8 + gr) * 68 + ni * 8 + 2 * tc) = pp;
                }
                rs += __shfl_xor_sync(0xffffffffu, rs, 1);
                rs += __shfl_xor_sync(0xffffffffu, rs, 2);
                lrow[mi][rr] = lrow[mi][rr] * corr + rs;
            }
        __syncwarp();

        // ---- PV: Oc += P @ V (B fragments read transposed from natural Vs) ----
#pragma unroll
        for (int kk = 0; kk < 8; ++kk) {
            uint32_t pf[2][4], vfv[8][2];
#pragma unroll
            for (int mi = 0; mi < 2; ++mi) {
                const int pa = (mi * 16 + gr) * 68 + kk * 8 + tc;
                pf[mi][0] = Pw[pa];
                pf[mi][1] = Pw[pa + 8 * 68];
                pf[mi][2] = Pw[pa + 4];
                pf[mi][3] = Pw[pa + 8 * 68 + 4];
            }
#pragma unroll
            for (int ni = 0; ni < 8; ++ni) {
                vfv[ni][0] = Vs[(kk * 8 + tc) * VST + ni * 8 + gr];
                vfv[ni][1] = Vs[(kk * 8 + tc + 4) * VST + ni * 8 + gr];
            }
#pragma unroll
            for (int mi = 0; mi < 2; ++mi)
#pragma unroll
                for (int ni = 0; ni < 8; ++ni)
                    mma8(Oc[mi][ni], pf[mi][0], pf[mi][1], pf[mi][2], pf[mi][3],
                         vfv[ni][0], vfv[ni][1]);
        }
    }

    // ---- normalize + store to g_att [B,S,E] ----
    const int b = bh >> 4, hh = bh & 15;
#pragma unroll
    for (int mi = 0; mi < 2; ++mi)
#pragma unroll
        for (int rr = 0; rr < 2; ++rr) {
            const float inv = 1.0f / lrow[mi][rr];
            const int row = wrow + mi * 16 + rr * 8 + gr;
            float* og = g_att + (size_t)(b * SS + row) * EE + hh * 64;
#pragma unroll
            for (int ni = 0; ni < 8; ++ni) {
                float2 o;
                o.x = Oc[mi][ni][rr * 2]     * inv;
                o.y = Oc[mi][ni][rr * 2 + 1] * inv;
                *(float2*)(og + ni * 8 + 2 * tc) = o;
            }
        }
}

// ---------------------------------------------------------------------------
extern "C" void kernel_launch(void* const* d_in, const int* in_sizes, int n_in,
                              void* d_out, int out_size)
{
    const float* x     = (const float*)d_in[0];
    const float* qkv_w = (const float*)d_in[1];
    const float* qkv_b = (const float*)d_in[2];
    const float* out_w = (const float*)d_in[3];
    const float* out_b = (const float*)d_in[4];
    float* out = (float*)d_out;

    cudaFuncSetAttribute(gemm_mma<0>, cudaFuncAttributeMaxDynamicSharedMemorySize, GEMM_SMEM);
    cudaFuncSetAttribute(gemm_mma<1>, cudaFuncAttributeMaxDynamicSharedMemorySize, GEMM_SMEM);
    cudaFuncSetAttribute(attn_mma, cudaFuncAttributeMaxDynamicSharedMemorySize, ATTN_SMEM);

    // 1) fused QKV projection -> g_q (tf32,scaled) / g_khi,g_klo / g_v
    gemm_mma<0><<<dim3(3072 / 256, MROWS / 128), 256, GEMM_SMEM>>>(
        x, qkv_w, qkv_b, nullptr, 3 * EE);

    // 2) causal flash attention (tf32 mma.sync) -> g_att [B,S,E]
    attn_mma<<<dim3(SS / 128, BB * HH), 128, ATTN_SMEM>>>();

    // 3) output projection
    gemm_mma<1><<<dim3(EE / 256, MROWS / 128), 256, GEMM_SMEM>>>(
        nullptr, out_w, out_b, out, EE);
}